// round 16
// baseline (speedup 1.0000x reference)
#include <cuda_runtime.h>
#include <cuda_fp16.h>
#include <math.h>
#include <stdint.h>

// ---------------- problem constants ----------------
#define T_    2048
#define HID_  2048
#define H_    16
#define DN_   128
#define DR_   64
#define DQK_  192
#define DV_   128
#define QLR_  1536
#define KVLR_ 512
#define INTER_ 10944
#define EPS_  1e-6f
#define SCALE_ 0.07216878364870323f   // 192^-0.5
#define NCAT_ (QLR_ + KVLR_ + DR_)    // 2112

// ---------------- fp32 scratch ----------------
__device__ float g_qa[(size_t)T_ * QLR_];
__device__ float g_ckv[(size_t)T_ * (KVLR_ + DR_)];
__device__ float g_res2[(size_t)T_ * HID_];
// ---------------- fp16 scratch ----------------
__device__ __half g_hh[(size_t)T_ * HID_];
__device__ __half g_qah[(size_t)T_ * QLR_];
__device__ __half g_ckvnh[(size_t)T_ * KVLR_];
__device__ __half g_qh[(size_t)T_ * H_ * DQK_];
__device__ __half g_kvh[(size_t)T_ * H_ * (DN_ + DV_)];
__device__ __half g_qfullh[(size_t)H_ * T_ * DQK_];
__device__ __half g_kfullh[(size_t)H_ * T_ * DQK_];
__device__ __half g_vth[(size_t)H_ * DV_ * T_];
__device__ __half g_attnh[(size_t)T_ * H_ * DV_];
__device__ __half g_h2h[(size_t)T_ * HID_];
__device__ __half g_acth[(size_t)T_ * INTER_];
// fp16 weights (only the ones still pre-converted)
__device__ __half g_wcat[(size_t)NCAT_ * HID_];     // [w_q_a ; w_kv_a]
__device__ __half g_wqb[(size_t)H_ * DQK_ * QLR_];
__device__ __half g_wkvb[(size_t)H_ * (DN_ + DV_) * KVLR_];
__device__ __half g_wo[(size_t)HID_ * H_ * DV_];

// ---------------- helpers ----------------
__device__ __forceinline__ uint32_t smem_u32(const void* p) {
    uint32_t a;
    asm("{ .reg .u64 t; cvta.to.shared.u64 t, %1; cvt.u32.u64 %0, t; }" : "=r"(a) : "l"(p));
    return a;
}
__device__ __forceinline__ void ldsm4(uint32_t addr, uint32_t& r0, uint32_t& r1,
                                      uint32_t& r2, uint32_t& r3) {
    asm volatile("ldmatrix.sync.aligned.m8n8.x4.shared.b16 {%0,%1,%2,%3}, [%4];"
                 : "=r"(r0), "=r"(r1), "=r"(r2), "=r"(r3) : "r"(addr));
}
__device__ __forceinline__ void mma_f16(float* c, const uint32_t* a, const uint32_t* b) {
    asm volatile(
        "mma.sync.aligned.m16n8k16.row.col.f32.f16.f16.f32 "
        "{%0,%1,%2,%3}, {%4,%5,%6,%7}, {%8,%9}, {%0,%1,%2,%3};"
        : "+f"(c[0]), "+f"(c[1]), "+f"(c[2]), "+f"(c[3])
        : "r"(a[0]), "r"(a[1]), "r"(a[2]), "r"(a[3]), "r"(b[0]), "r"(b[1]));
}
__device__ __forceinline__ void cp16(uint32_t smaddr, const void* gaddr, int vbytes) {
    asm volatile("cp.async.cg.shared.global [%0], [%1], 16, %2;"
                 :: "r"(smaddr), "l"(gaddr), "r"(vbytes) : "memory");
}
#define CP_COMMIT() asm volatile("cp.async.commit_group;" ::: "memory")
#define CP_WAIT1()  asm volatile("cp.async.wait_group 1;" ::: "memory")

__device__ __forceinline__ uint4 cvt8(const float* p) {
    float4 a = ((const float4*)p)[0], b = ((const float4*)p)[1];
    __half2 h0 = __floats2half2_rn(a.x, a.y), h1 = __floats2half2_rn(a.z, a.w);
    __half2 h2 = __floats2half2_rn(b.x, b.y), h3 = __floats2half2_rn(b.z, b.w);
    uint4 u;
    u.x = *(uint32_t*)&h0; u.y = *(uint32_t*)&h1;
    u.z = *(uint32_t*)&h2; u.w = *(uint32_t*)&h3;
    return u;
}

// ================= fp16 mma.sync GEMM: C = A * B^T (B fp16) =================
// Block 128x128, 4 warps (2x2), warp tile 64x64, BK=64, 3-stage cp.async.
// mode: 0 dense; 2 causal K-truncate.
// emode: 0 fp32 C; 1 half C; 2 fp32 C = acc + R;
//        5 split fp32: col<QLR_ -> Cv[ld=QLR_], else -> R[ld=KVLR_+DR_].
#define GH_A_BYTES 16384
#define GH_STAGE_BYTES 32768
#define GH_SMEM (3 * GH_STAGE_BYTES)

__global__ __launch_bounds__(128, 2) void gemm_h(
    const __half* __restrict__ A, int lda, size_t sA,
    const __half* __restrict__ B, int ldb, size_t sB,
    void* __restrict__ Cv, int ldc, size_t sC,
    const float* __restrict__ R,
    int M, int N, int K, int mode, int emode)
{
    const int bm = blockIdx.y, bn = blockIdx.x, bz = blockIdx.z;
    int kEnd = K;
    if (mode == 2) { int ke = (bm + 1) * 128; kEnd = ke < K ? ke : K; }

    A += (size_t)bz * sA;
    B += (size_t)bz * sB;

    extern __shared__ char smem[];
    const uint32_t smem_base = smem_u32(smem);
    const int tid = threadIdx.x, wid = tid >> 5, lane = tid & 31;
    const int wm = wid & 1, wn = wid >> 1;
    const int row0 = bm * 128, nrow0 = bn * 128;
    const int nIter = kEnd >> 6;

    const int lr = tid >> 3;
    const int lc = tid & 7;
    const uint32_t lsw = (uint32_t)((lc ^ (lr & 7)) << 4);

    auto load_stage = [&](int it, int s) {
        const int k0 = it << 6;
        const uint32_t sA_ = smem_base + s * GH_STAGE_BYTES;
        const uint32_t sB_ = sA_ + GH_A_BYTES;
#pragma unroll
        for (int j = 0; j < 8; j++) {
            const int r = lr + j * 16;
            cp16(sA_ + (uint32_t)r * 128 + lsw,
                 A + (size_t)(row0 + r) * lda + k0 + lc * 8, 16);
        }
#pragma unroll
        for (int j = 0; j < 8; j++) {
            const int r = lr + j * 16;
            const int gr = nrow0 + r;
            cp16(sB_ + (uint32_t)r * 128 + lsw,
                 B + (size_t)(gr < N ? gr : 0) * ldb + k0 + lc * 8, gr < N ? 16 : 0);
        }
        CP_COMMIT();
    };

    float acc[4][8][4];
#pragma unroll
    for (int i = 0; i < 4; i++)
#pragma unroll
        for (int j = 0; j < 8; j++)
#pragma unroll
            for (int l = 0; l < 4; l++) acc[i][j][l] = 0.f;

    load_stage(0, 0);
    if (1 < nIter) load_stage(1, 1); else CP_COMMIT();

    const int l15 = lane & 15;
    const int achk = lane >> 4;
    const int brow_lo = (lane & 7) + ((lane >> 4) << 3);
    const int bchk = (lane >> 3) & 1;

    for (int it = 0; it < nIter; ++it) {
        CP_WAIT1();
        __syncthreads();
        if (it + 2 < nIter) load_stage(it + 2, (it + 2) % 3); else CP_COMMIT();

        const uint32_t bA = smem_base + (it % 3) * GH_STAGE_BYTES;
        const uint32_t bB = bA + GH_A_BYTES;
#pragma unroll
        for (int ks = 0; ks < 4; ks++) {
            uint32_t a[4][4];
#pragma unroll
            for (int mt = 0; mt < 4; mt++) {
                const int row = wm * 64 + mt * 16 + l15;
                const int chk = ks * 2 + achk;
                const uint32_t addr = bA + (uint32_t)row * 128 +
                                      (uint32_t)((chk ^ (row & 7)) << 4);
                ldsm4(addr, a[mt][0], a[mt][1], a[mt][2], a[mt][3]);
            }
            uint32_t b[8][2];
#pragma unroll
            for (int np = 0; np < 4; np++) {
                const int row = wn * 64 + np * 16 + brow_lo;
                const int chk = ks * 2 + bchk;
                const uint32_t addr = bB + (uint32_t)row * 128 +
                                      (uint32_t)((chk ^ (row & 7)) << 4);
                uint32_t q0, q1, q2, q3;
                ldsm4(addr, q0, q1, q2, q3);
                b[np * 2][0] = q0;     b[np * 2][1] = q1;
                b[np * 2 + 1][0] = q2; b[np * 2 + 1][1] = q3;
            }
#pragma unroll
            for (int mt = 0; mt < 4; mt++)
#pragma unroll
                for (int nt = 0; nt < 8; nt++)
                    mma_f16(acc[mt][nt], a[mt], b[nt]);
        }
    }

    // epilogue
    const int g = lane >> 2, t = lane & 3;
    float* Cf = (float*)Cv + (size_t)bz * sC;
    __half* Ch = (__half*)Cv + (size_t)bz * sC;
#pragma unroll
    for (int mt = 0; mt < 4; mt++) {
#pragma unroll
        for (int nt = 0; nt < 8; nt++) {
            const int r0 = row0 + wm * 64 + mt * 16 + g;
            const int c0 = nrow0 + wn * 64 + nt * 8 + 2 * t;
            if (c0 < N) {
                float v0 = acc[mt][nt][0], v1 = acc[mt][nt][1];
                float v2 = acc[mt][nt][2], v3 = acc[mt][nt][3];
                if (emode == 2) {
                    const float2 u0 = *(const float2*)&R[(size_t)r0 * ldc + c0];
                    const float2 u1 = *(const float2*)&R[(size_t)(r0 + 8) * ldc + c0];
                    v0 += u0.x; v1 += u0.y; v2 += u1.x; v3 += u1.y;
                }
                if (emode == 1) {
                    *(__half2*)&Ch[(size_t)r0 * ldc + c0] = __floats2half2_rn(v0, v1);
                    *(__half2*)&Ch[(size_t)(r0 + 8) * ldc + c0] = __floats2half2_rn(v2, v3);
                } else if (emode == 5) {
                    if (c0 < QLR_) {
                        *(float2*)&Cf[(size_t)r0 * QLR_ + c0] = make_float2(v0, v1);
                        *(float2*)&Cf[(size_t)(r0 + 8) * QLR_ + c0] = make_float2(v2, v3);
                    } else {
                        float* Ck = (float*)R;
                        const int cc = c0 - QLR_;
                        *(float2*)&Ck[(size_t)r0 * (KVLR_ + DR_) + cc] = make_float2(v0, v1);
                        *(float2*)&Ck[(size_t)(r0 + 8) * (KVLR_ + DR_) + cc] = make_float2(v2, v3);
                    }
                } else {
                    *(float2*)&Cf[(size_t)r0 * ldc + c0] = make_float2(v0, v1);
                    *(float2*)&Cf[(size_t)(r0 + 8) * ldc + c0] = make_float2(v2, v3);
                }
            }
        }
    }
}

// ====== gemm_dn: C = acc + R with B in fp32 (converted in the loader) ======
__global__ __launch_bounds__(128, 2) void gemm_dn(
    const __half* __restrict__ A,
    const float* __restrict__ B,
    float* __restrict__ C,
    const float* __restrict__ R,
    int M, int N, int K)
{
    const int bm = blockIdx.y, bn = blockIdx.x;
    extern __shared__ char smem[];
    const uint32_t smem_base = smem_u32(smem);
    const int tid = threadIdx.x, wid = tid >> 5, lane = tid & 31;
    const int wm = wid & 1, wn = wid >> 1;
    const int row0 = bm * 128, nrow0 = bn * 128;
    const int nIter = K >> 6;

    const int lr = tid >> 3;
    const int lc = tid & 7;
    const uint32_t lsw = (uint32_t)((lc ^ (lr & 7)) << 4);

    auto load_stage = [&](int it, int s) {
        const int k0 = it << 6;
        const uint32_t sA_ = smem_base + s * GH_STAGE_BYTES;
        char* sBp = smem + s * GH_STAGE_BYTES + GH_A_BYTES;
#pragma unroll
        for (int j = 0; j < 8; j++) {
            const int r = lr + j * 16;
            cp16(sA_ + (uint32_t)r * 128 + lsw,
                 A + (size_t)(row0 + r) * K + k0 + lc * 8, 16);
        }
        CP_COMMIT();
#pragma unroll
        for (int j = 0; j < 8; j++) {
            const int r = lr + j * 16;
            const int gr = nrow0 + r;
            const float* src = B + (size_t)gr * K + k0 + lc * 8;
            *(uint4*)(sBp + (uint32_t)r * 128 + lsw) = cvt8(src);
        }
    };

    float acc[4][8][4];
#pragma unroll
    for (int i = 0; i < 4; i++)
#pragma unroll
        for (int j = 0; j < 8; j++)
#pragma unroll
            for (int l = 0; l < 4; l++) acc[i][j][l] = 0.f;

    load_stage(0, 0);
    if (1 < nIter) load_stage(1, 1); else CP_COMMIT();

    const int l15 = lane & 15;
    const int achk = lane >> 4;
    const int brow_lo = (lane & 7) + ((lane >> 4) << 3);
    const int bchk = (lane >> 3) & 1;

    for (int it = 0; it < nIter; ++it) {
        CP_WAIT1();
        __syncthreads();
        if (it + 2 < nIter) load_stage(it + 2, (it + 2) % 3); else CP_COMMIT();

        const uint32_t bA = smem_base + (it % 3) * GH_STAGE_BYTES;
        const uint32_t bB = bA + GH_A_BYTES;
#pragma unroll
        for (int ks = 0; ks < 4; ks++) {
            uint32_t a[4][4];
#pragma unroll
            for (int mt = 0; mt < 4; mt++) {
                const int row = wm * 64 + mt * 16 + l15;
                const int chk = ks * 2 + achk;
                const uint32_t addr = bA + (uint32_t)row * 128 +
                                      (uint32_t)((chk ^ (row & 7)) << 4);
                ldsm4(addr, a[mt][0], a[mt][1], a[mt][2], a[mt][3]);
            }
            uint32_t b[8][2];
#pragma unroll
            for (int np = 0; np < 4; np++) {
                const int row = wn * 64 + np * 16 + brow_lo;
                const int chk = ks * 2 + bchk;
                const uint32_t addr = bB + (uint32_t)row * 128 +
                                      (uint32_t)((chk ^ (row & 7)) << 4);
                uint32_t q0, q1, q2, q3;
                ldsm4(addr, q0, q1, q2, q3);
                b[np * 2][0] = q0;     b[np * 2][1] = q1;
                b[np * 2 + 1][0] = q2; b[np * 2 + 1][1] = q3;
            }
#pragma unroll
            for (int mt = 0; mt < 4; mt++)
#pragma unroll
                for (int nt = 0; nt < 8; nt++)
                    mma_f16(acc[mt][nt], a[mt], b[nt]);
        }
    }

    const int g = lane >> 2, t = lane & 3;
#pragma unroll
    for (int mt = 0; mt < 4; mt++) {
#pragma unroll
        for (int nt = 0; nt < 8; nt++) {
            const int r0 = row0 + wm * 64 + mt * 16 + g;
            const int c0 = nrow0 + wn * 64 + nt * 8 + 2 * t;
            const float2 u0 = *(const float2*)&R[(size_t)r0 * N + c0];
            const float2 u1 = *(const float2*)&R[(size_t)(r0 + 8) * N + c0];
            *(float2*)&C[(size_t)r0 * N + c0] =
                make_float2(acc[mt][nt][0] + u0.x, acc[mt][nt][1] + u0.y);
            *(float2*)&C[(size_t)(r0 + 8) * N + c0] =
                make_float2(acc[mt][nt][2] + u1.x, acc[mt][nt][3] + u1.y);
        }
    }
}

// ======== fused gate/up GEMM, B fp32 (converted in loader) ========
#define GU_A_BYTES 16384
#define GU_B_BYTES 8192
#define GU_STAGE_BYTES 32768
#define GU_SMEM (3 * GU_STAGE_BYTES)

__global__ __launch_bounds__(128, 2) void gemm_gu(
    const __half* __restrict__ A,
    const float* __restrict__ Bg,
    const float* __restrict__ Bu,
    __half* __restrict__ C,
    int M, int N, int K)
{
    const int bm = blockIdx.y, bn = blockIdx.x;
    extern __shared__ char smem[];
    const uint32_t smem_base = smem_u32(smem);
    const int tid = threadIdx.x, wid = tid >> 5, lane = tid & 31;
    const int wm = wid & 1, wn = wid >> 1;
    const int row0 = bm * 128, ncol0 = bn * 64;
    const int nIter = K >> 6;

    const int lr = tid >> 3;
    const int lc = tid & 7;
    const uint32_t lsw = (uint32_t)((lc ^ (lr & 7)) << 4);

    auto load_stage = [&](int it, int s) {
        const int k0 = it << 6;
        const uint32_t sA_ = smem_base + s * GU_STAGE_BYTES;
        char* sGp = smem + s * GU_STAGE_BYTES + GU_A_BYTES;
        char* sUp = sGp + GU_B_BYTES;
#pragma unroll
        for (int j = 0; j < 8; j++) {
            const int r = lr + j * 16;
            cp16(sA_ + (uint32_t)r * 128 + lsw,
                 A + (size_t)(row0 + r) * K + k0 + lc * 8, 16);
        }
        CP_COMMIT();
#pragma unroll
        for (int j = 0; j < 4; j++) {
            const int r = lr + j * 16;
            const int gr = ncol0 + r;
            *(uint4*)(sGp + (uint32_t)r * 128 + lsw) = cvt8(Bg + (size_t)gr * K + k0 + lc * 8);
            *(uint4*)(sUp + (uint32_t)r * 128 + lsw) = cvt8(Bu + (size_t)gr * K + k0 + lc * 8);
        }
    };

    float accg[4][4][4], accu[4][4][4];
#pragma unroll
    for (int i = 0; i < 4; i++)
#pragma unroll
        for (int j = 0; j < 4; j++)
#pragma unroll
            for (int l = 0; l < 4; l++) { accg[i][j][l] = 0.f; accu[i][j][l] = 0.f; }

    load_stage(0, 0);
    if (1 < nIter) load_stage(1, 1); else CP_COMMIT();

    const int l15 = lane & 15;
    const int achk = lane >> 4;
    const int brow_lo = (lane & 7) + ((lane >> 4) << 3);
    const int bchk = (lane >> 3) & 1;

    for (int it = 0; it < nIter; ++it) {
        CP_WAIT1();
        __syncthreads();
        if (it + 2 < nIter) load_stage(it + 2, (it + 2) % 3); else CP_COMMIT();

        const uint32_t bA = smem_base + (it % 3) * GU_STAGE_BYTES;
        const uint32_t bG = bA + GU_A_BYTES;
        const uint32_t bU = bG + GU_B_BYTES;
#pragma unroll
        for (int ks = 0; ks < 4; ks++) {
            uint32_t a[4][4];
#pragma unroll
            for (int mt = 0; mt < 4; mt++) {
                const int row = wm * 64 + mt * 16 + l15;
                const int chk = ks * 2 + achk;
                const uint32_t addr = bA + (uint32_t)row * 128 +
                                      (uint32_t)((chk ^ (row & 7)) << 4);
                ldsm4(addr, a[mt][0], a[mt][1], a[mt][2], a[mt][3]);
            }
            uint32_t bg[4][2], bu[4][2];
#pragma unroll
            for (int np = 0; np < 2; np++) {
                const int row = wn * 32 + np * 16 + brow_lo;
                const int chk = ks * 2 + bchk;
                const uint32_t swo = (uint32_t)row * 128 + (uint32_t)((chk ^ (row & 7)) << 4);
                uint32_t q0, q1, q2, q3;
                ldsm4(bG + swo, q0, q1, q2, q3);
                bg[np * 2][0] = q0;     bg[np * 2][1] = q1;
                bg[np * 2 + 1][0] = q2; bg[np * 2 + 1][1] = q3;
                ldsm4(bU + swo, q0, q1, q2, q3);
                bu[np * 2][0] = q0;     bu[np * 2][1] = q1;
                bu[np * 2 + 1][0] = q2; bu[np * 2 + 1][1] = q3;
            }
#pragma unroll
            for (int mt = 0; mt < 4; mt++)
#pragma unroll
                for (int nt = 0; nt < 4; nt++) {
                    mma_f16(accg[mt][nt], a[mt], bg[nt]);
                    mma_f16(accu[mt][nt], a[mt], bu[nt]);
                }
        }
    }

    const int g = lane >> 2, t = lane & 3;
#pragma unroll
    for (int mt = 0; mt < 4; mt++) {
#pragma unroll
        for (int nt = 0; nt < 4; nt++) {
            const int r0 = row0 + wm * 64 + mt * 16 + g;
            const int c0 = ncol0 + wn * 32 + nt * 8 + 2 * t;
            float g0 = accg[mt][nt][0], g1 = accg[mt][nt][1];
            float g2 = accg[mt][nt][2], g3 = accg[mt][nt][3];
            float v0 = g0 / (1.f + expf(-g0)) * accu[mt][nt][0];
            float v1 = g1 / (1.f + expf(-g1)) * accu[mt][nt][1];
            float v2 = g2 / (1.f + expf(-g2)) * accu[mt][nt][2];
            float v3 = g3 / (1.f + expf(-g3)) * accu[mt][nt][3];
            *(__half2*)&C[(size_t)r0 * N + c0] = __floats2half2_rn(v0, v1);
            *(__half2*)&C[(size_t)(r0 + 8) * N + c0] = __floats2half2_rn(v2, v3);
        }
    }
}

// ================= fused flash attention =================
#define FA_QP 0
#define FA_KP 49152
#define FA_VP 147456
#define FA_SMEM 212992

__global__ __launch_bounds__(256, 1) void flash_kernel(
    const __half* __restrict__ Qf, const __half* __restrict__ Kf,
    const __half* __restrict__ Vt, __half* __restrict__ O)
{
    const int qb = (int)gridDim.y - 1 - blockIdx.y;
    const int h = blockIdx.x;
    const int nb = qb + 1;
    const int q0 = qb * 128;
    extern __shared__ char smem[];
    const uint32_t sb = smem_u32(smem);
    const int tid = threadIdx.x, wid = tid >> 5, lane = tid & 31;
    const int lr = tid >> 3, lc = tid & 7;

    const __half* Qb = Qf + (size_t)h * T_ * DQK_;
    const __half* Kb = Kf + (size_t)h * T_ * DQK_;
    const __half* Vb = Vt + (size_t)h * DV_ * T_;

    auto swz = [](int row, int chk) -> uint32_t {
        return (uint32_t)(row * 128 + ((chk ^ (row & 7)) << 4));
    };

#pragma unroll
    for (int p = 0; p < 3; p++)
#pragma unroll
        for (int j = 0; j < 4; j++) {
            const int r = lr + j * 32;
            cp16(sb + FA_QP + p * 16384 + swz(r, lc),
                 Qb + (size_t)(q0 + r) * DQK_ + p * 64 + lc * 8, 16);
        }
    auto loadKV = [&](int kb, int st) {
        const int k0 = kb * 128;
#pragma unroll
        for (int p = 0; p < 3; p++)
#pragma unroll
            for (int j = 0; j < 4; j++) {
                const int r = lr + j * 32;
                cp16(sb + FA_KP + st * 49152 + p * 16384 + swz(r, lc),
                     Kb + (size_t)(k0 + r) * DQK_ + p * 64 + lc * 8, 16);
            }
#pragma unroll
        for (int p = 0; p < 2; p++)
#pragma unroll
            for (int j = 0; j < 4; j++) {
                const int dv = lr + j * 32;
                cp16(sb + FA_VP + st * 32768 + p * 16384 + swz(dv, lc),
                     Vb + (size_t)dv * T_ + k0 + p * 64 + lc * 8, 16);
            }
    };
    loadKV(0, 0);
    CP_COMMIT();

    float m0 = -1e30f, m1 = -1e30f, l0 = 0.f, l1 = 0.f;
    float o[16][4];
#pragma unroll
    for (int i = 0; i < 16; i++)
#pragma unroll
        for (int e = 0; e < 4; e++) o[i][e] = 0.f;

    const int l15 = lane & 15;
    const int achk = lane >> 4;
    const int brow_lo = (lane & 7) + ((lane >> 4) << 3);
    const int bchk = (lane >> 3) & 1;
    const int g = lane >> 2, t4 = lane & 3;
    const int rowA = wid * 16 + l15;
    const int gq0 = q0 + wid * 16 + g;

    for (int kb = 0; kb < nb; kb++) {
        if (kb + 1 < nb) loadKV(kb + 1, (kb + 1) & 1);
        CP_COMMIT();
        CP_WAIT1();
        __syncthreads();

        const uint32_t bK = sb + FA_KP + (kb & 1) * 49152;
        const uint32_t bV = sb + FA_VP + (kb & 1) * 32768;

        float sacc[16][4];
#pragma unroll
        for (int i = 0; i < 16; i++)
#pragma unroll
            for (int e = 0; e < 4; e++) sacc[i][e] = 0.f;

#pragma unroll
        for (int p = 0; p < 3; p++) {
            const uint32_t qp = sb + FA_QP + p * 16384;
            const uint32_t kp = bK + p * 16384;
#pragma unroll
            for (int sl = 0; sl < 4; sl++) {
                uint32_t a[4];
                ldsm4(qp + swz(rowA, sl * 2 + achk), a[0], a[1], a[2], a[3]);
                uint32_t b[16][2];
#pragma unroll
                for (int np = 0; np < 8; np++) {
                    uint32_t r0, r1, r2, r3;
                    ldsm4(kp + swz(np * 16 + brow_lo, sl * 2 + bchk), r0, r1, r2, r3);
                    b[2 * np][0] = r0;     b[2 * np][1] = r1;
                    b[2 * np + 1][0] = r2; b[2 * np + 1][1] = r3;
                }
#pragma unroll
                for (int nt = 0; nt < 16; nt++)
                    mma_f16(sacc[nt], a, b[nt]);
            }
        }

        const int k0 = kb * 128;
#pragma unroll
        for (int nt = 0; nt < 16; nt++) {
            const int c = k0 + nt * 8 + 2 * t4;
            float s0 = sacc[nt][0] * SCALE_, s1 = sacc[nt][1] * SCALE_;
            float s2 = sacc[nt][2] * SCALE_, s3 = sacc[nt][3] * SCALE_;
            if (kb == qb) {
                if (c     > gq0)     s0 = -1e30f;
                if (c + 1 > gq0)     s1 = -1e30f;
                if (c     > gq0 + 8) s2 = -1e30f;
                if (c + 1 > gq0 + 8) s3 = -1e30f;
            }
            sacc[nt][0] = s0; sacc[nt][1] = s1; sacc[nt][2] = s2; sacc[nt][3] = s3;
        }
        float mx0 = -1e30f, mx1 = -1e30f;
#pragma unroll
        for (int nt = 0; nt < 16; nt++) {
            mx0 = fmaxf(mx0, fmaxf(sacc[nt][0], sacc[nt][1]));
            mx1 = fmaxf(mx1, fmaxf(sacc[nt][2], sacc[nt][3]));
        }
        mx0 = fmaxf(mx0, __shfl_xor_sync(0xffffffffu, mx0, 1));
        mx0 = fmaxf(mx0, __shfl_xor_sync(0xffffffffu, mx0, 2));
        mx1 = fmaxf(mx1, __shfl_xor_sync(0xffffffffu, mx1, 1));
        mx1 = fmaxf(mx1, __shfl_xor_sync(0xffffffffu, mx1, 2));
        const float mn0 = fmaxf(m0, mx0), mn1 = fmaxf(m1, mx1);
        const float f0 = __expf(m0 - mn0), f1 = __expf(m1 - mn1);
        m0 = mn0; m1 = mn1;
        float rs0 = 0.f, rs1 = 0.f;
#pragma unroll
        for (int nt = 0; nt < 16; nt++) {
            const float p0 = __expf(sacc[nt][0] - mn0);
            const float p1 = __expf(sacc[nt][1] - mn0);
            const float p2 = __expf(sacc[nt][2] - mn1);
            const float p3 = __expf(sacc[nt][3] - mn1);
            sacc[nt][0] = p0; sacc[nt][1] = p1; sacc[nt][2] = p2; sacc[nt][3] = p3;
            rs0 += p0 + p1; rs1 += p2 + p3;
            o[nt][0] *= f0; o[nt][1] *= f0; o[nt][2] *= f1; o[nt][3] *= f1;
        }
        rs0 += __shfl_xor_sync(0xffffffffu, rs0, 1);
        rs0 += __shfl_xor_sync(0xffffffffu, rs0, 2);
        rs1 += __shfl_xor_sync(0xffffffffu, rs1, 1);
        rs1 += __shfl_xor_sync(0xffffffffu, rs1, 2);
        l0 = l0 * f0 + rs0;
        l1 = l1 * f1 + rs1;

#pragma unroll
        for (int s8 = 0; s8 < 8; s8++) {
            uint32_t pa[4];
            __half2 ph0 = __floats2half2_rn(sacc[2 * s8][0], sacc[2 * s8][1]);
            __half2 ph1 = __floats2half2_rn(sacc[2 * s8][2], sacc[2 * s8][3]);
            __half2 ph2 = __floats2half2_rn(sacc[2 * s8 + 1][0], sacc[2 * s8 + 1][1]);
            __half2 ph3 = __floats2half2_rn(sacc[2 * s8 + 1][2], sacc[2 * s8 + 1][3]);
            pa[0] = *(uint32_t*)&ph0; pa[1] = *(uint32_t*)&ph1;
            pa[2] = *(uint32_t*)&ph2; pa[3] = *(uint32_t*)&ph3;
            const int pp = s8 >> 2, chk = (s8 & 3) * 2;
            uint32_t bv[16][2];
#pragma unroll
            for (int np = 0; np < 8; np++) {
                uint32_t r0, r1, r2, r3;
                ldsm4(bV + pp * 16384 + swz(np * 16 + brow_lo, chk + bchk), r0, r1, r2, r3);
                bv[2 * np][0] = r0;     bv[2 * np][1] = r1;
                bv[2 * np + 1][0] = r2; bv[2 * np + 1][1] = r3;
            }
#pragma unroll
            for (int nt = 0; nt < 16; nt++)
                mma_f16(o[nt], pa, bv[nt]);
        }
        __syncthreads();
    }

    const float i0 = 1.f / l0, i1 = 1.f / l1;
    const int r = q0 + wid * 16 + g;
#pragma unroll
    for (int nt = 0; nt < 16; nt++) {
        const int c = h * DV_ + nt * 8 + 2 * t4;
        *(__half2*)&O[(size_t)r * (H_ * DV_) + c] =
            __floats2half2_rn(o[nt][0] * i0, o[nt][1] * i0);
        *(__half2*)&O[(size_t)(r + 8) * (H_ * DV_) + c] =
            __floats2half2_rn(o[nt][2] * i1, o[nt][3] * i1);
    }
}

// ---------- merged fp32 -> fp16 conversion (remaining 5 weights) ----------
#define CVT_NREG 5
struct CvtTab {
    const float4* src[CVT_NREG];
    uint4* dst[CVT_NREG];
    unsigned long long end[CVT_NREG];
};

__global__ void cvt_all_kernel(CvtTab tab)
{
    const size_t i = (size_t)blockIdx.x * blockDim.x + threadIdx.x;
    if (i >= tab.end[CVT_NREG - 1]) return;
    int r = 0;
    while (i >= tab.end[r]) r++;
    const size_t local = i - (r ? tab.end[r - 1] : 0ull);
    const float4* p = tab.src[r] + 4 * local;
    float4 a = p[0], b = p[1], c = p[2], d = p[3];
    __half2 h0 = __floats2half2_rn(a.x, a.y), h1 = __floats2half2_rn(a.z, a.w);
    __half2 h2 = __floats2half2_rn(b.x, b.y), h3 = __floats2half2_rn(b.z, b.w);
    __half2 h4 = __floats2half2_rn(c.x, c.y), h5 = __floats2half2_rn(c.z, c.w);
    __half2 h6 = __floats2half2_rn(d.x, d.y), h7 = __floats2half2_rn(d.z, d.w);
    uint4 o0, o1;
    o0.x = *(uint32_t*)&h0; o0.y = *(uint32_t*)&h1;
    o0.z = *(uint32_t*)&h2; o0.w = *(uint32_t*)&h3;
    o1.x = *(uint32_t*)&h4; o1.y = *(uint32_t*)&h5;
    o1.z = *(uint32_t*)&h6; o1.w = *(uint32_t*)&h7;
    tab.dst[r][2 * local] = o0;
    tab.dst[r][2 * local + 1] = o1;
}

// ---------------- rmsnorm (float4-vectorized fp32 in -> fp16 out) -------------
__global__ void rmsnorm_kernel(const float* __restrict__ x, int ldx,
                               const float* __restrict__ w,
                               __half* __restrict__ out, int ldo, int dim)
{
    const int row = blockIdx.x;
    const float4* xr = (const float4*)(x + (size_t)row * ldx);
    const float4* w4 = (const float4*)w;
    const int n4 = dim >> 2;
    float4 v[2];
    float ss = 0.f;
    int cnt = 0;
    for (int i = threadIdx.x; i < n4; i += blockDim.x, cnt++) {
        float4 t = xr[i];
        v[cnt] = t;
        ss += t.x * t.x + t.y * t.y + t.z * t.z + t.w * t.w;
    }
    __shared__ float red[256];
    red[threadIdx.x] = ss;
    __syncthreads();
    for (int s = 128; s > 0; s >>= 1) {
        if (threadIdx.x < s) red[threadIdx.x] += red[threadIdx.x + s];
        __syncthreads();
    }
    const float inv = rsqrtf(red[0] / (float)dim + EPS_);
    __half* o = out + (size_t)row * ldo;
    cnt = 0;
    for (int i = threadIdx.x; i < n4; i += blockDim.x, cnt++) {
        const float4 ww = w4[i];
        const float4 t = v[cnt];
        __half2 a = __floats2half2_rn(t.x * inv * ww.x, t.y * inv * ww.y);
        __half2 b = __floats2half2_rn(t.z * inv * ww.z, t.w * inv * ww.w);
        uint2 u;
        u.x = *(uint32_t*)&a; u.y = *(uint32_t*)&b;
        *(uint2*)&o[i * 4] = u;
    }
}

// ---------------- RoPE + pack ----------------
__global__ void rope_pack_kernel(const __half* __restrict__ q,
                                 const __half* __restrict__ kv,
                                 const float* __restrict__ ckv,
                                 const float* __restrict__ cosb,
                                 const float* __restrict__ sinb,
                                 __half* __restrict__ qfull,
                                 __half* __restrict__ kfull)
{
    const int t = blockIdx.x, h = blockIdx.y, j = threadIdx.x;
    const size_t o = ((size_t)h * T_ + t) * DQK_ + j;
    float qv, kvv;
    if (j < DN_) {
        qv  = __half2float(q[(size_t)t * (H_ * DQK_) + h * DQK_ + j]);
        kvv = __half2float(kv[(size_t)t * (H_ * (DN_ + DV_)) + h * (DN_ + DV_) + j]);
    } else {
        const int jj = j - DN_;
        const int p  = (jj < DR_ / 2) ? jj : jj - DR_ / 2;
        const float c = cosb[(size_t)t * DR_ + jj];
        const float s = sinb[(size_t)t * DR_ + jj];
        const size_t qb = (size_t)t * (H_ * DQK_) + h * DQK_ + DN_;
        const size_t kb = (size_t)t * (KVLR_ + DR_) + KVLR_;
        const float qe = __half2float(q[qb + 2 * p]), qo = __half2float(q[qb + 2 * p + 1]);
        const float ke = ckv[kb + 2 * p], ko = ckv[kb + 2 * p + 1];
        if (jj < DR_ / 2) { qv = qe * c - qo * s;  kvv = ke * c - ko * s; }
        else              { qv = qo * c + qe * s;  kvv = ko * c + ke * s; }
    }
    qfull[o] = __float2half_rn(qv);
    kfull[o] = __float2half_rn(kvv);
}

// ---------------- pack V^T via smem transpose ----------------
__global__ void pack_vt_kernel(const __half* __restrict__ kvh, __half* __restrict__ vt)
{
    __shared__ __half tile[32][33];
    const int t0 = blockIdx.x * 32, d0 = blockIdx.y * 32, h = blockIdx.z;
    const int tx = threadIdx.x, ty = threadIdx.y;
    for (int r = ty; r < 32; r += 8)
        tile[r][tx] = kvh[(size_t)(t0 + r) * (H_ * (DN_ + DV_)) + h * (DN_ + DV_) + DN_ + d0 + tx];
    __syncthreads();
    for (int r = ty; r < 32; r += 8)
        vt[((size_t)h * DV_ + d0 + r) * T_ + t0 + tx] = tile[tx][r];
}

// ---------------- host driver ----------------
static inline void* sym(const void* s)
{
    void* p = nullptr;
    cudaGetSymbolAddress(&p, s);
    return p;
}

extern "C" void kernel_launch(void* const* d_in, const int* in_sizes, int n_in,
                              void* d_out, int out_size)
{
    const float* hidden  = (const float*)d_in[0];
    const float* cosb    = (const float*)d_in[1];
    const float* sinb    = (const float*)d_in[2];
    const float* ln_in   = (const float*)d_in[3];
    const float* w_q_a   = (const float*)d_in[4];
    const float* ln_q_a  = (const float*)d_in[5];
    const float* w_q_b   = (const float*)d_in[6];
    const float* w_kv_a  = (const float*)d_in[7];
    const float* ln_kv_a = (const float*)d_in[8];
    const float* w_kv_b  = (const float*)d_in[9];
    const float* w_o     = (const float*)d_in[10];
    const float* ln_post = (const float*)d_in[11];
    const float* w_gate  = (const float*)d_in[12];
    const float* w_up    = (const float*)d_in[13];
    const float* w_down  = (const float*)d_in[14];
    float* out = (float*)d_out;

    float* qa    = (float*)sym(g_qa);
    float* ckv   = (float*)sym(g_ckv);
    float* res2  = (float*)sym(g_res2);
    __half* hh    = (__half*)sym(g_hh);
    __half* qah   = (__half*)sym(g_qah);
    __half* ckvnh = (__half*)sym(g_ckvnh);
    __half* qh    = (__half*)sym(g_qh);
    __half* kvh   = (__half*)sym(g_kvh);
    __half* qfh   = (__half*)sym(g_qfullh);
    __half* kfh   = (__half*)sym(g_kfullh);
    __half* vth   = (__half*)sym(g_vth);
    __half* ath   = (__half*)sym(g_attnh);
    __half* h2h   = (__half*)sym(g_h2h);
    __half* acth  = (__half*)sym(g_acth);
    __half* wcat  = (__half*)sym(g_wcat);
    __half* wqb   = (__half*)sym(g_wqb);
    __half* wkvb  = (__half*)sym(g_wkvb);
    __half* wo    = (__half*)sym(g_wo);

    cudaFuncSetAttribute(gemm_h, cudaFuncAttributeMaxDynamicSharedMemorySize, GH_SMEM);
    cudaFuncSetAttribute(gemm_dn, cudaFuncAttributeMaxDynamicSharedMemorySize, GH_SMEM);
    cudaFuncSetAttribute(gemm_gu, cudaFuncAttributeMaxDynamicSharedMemorySize, GU_SMEM);
    cudaFuncSetAttribute(flash_kernel, cudaFuncAttributeMaxDynamicSharedMemorySize, FA_SMEM);

    const int NB = 256;
    const int GB = 128;
    const int SH = GH_SMEM;
    auto grid2 = [](int M, int N) { return dim3((N + 127) / 128, M / 128, 1); };

    // ---- merged weight conversion (5 remaining regions, one launch) ----
    CvtTab tab;
    const float* srcs[CVT_NREG] = { w_q_a, w_kv_a, w_q_b, w_kv_b, w_o };
    __half* dsts[CVT_NREG] = { wcat, wcat + (size_t)QLR_ * HID_, wqb, wkvb, wo };
    const size_t sizes[CVT_NREG] = {
        (size_t)QLR_ * HID_, (size_t)(KVLR_ + DR_) * HID_,
        (size_t)H_ * DQK_ * QLR_, (size_t)H_ * (DN_ + DV_) * KVLR_,
        (size_t)HID_ * H_ * DV_ };
    unsigned long long acc16 = 0;
    for (int r = 0; r < CVT_NREG; r++) {
        tab.src[r] = (const float4*)srcs[r];
        tab.dst[r] = (uint4*)dsts[r];
        acc16 += sizes[r] / 16;
        tab.end[r] = acc16;
    }
    cvt_all_kernel<<<(unsigned)((acc16 + 255) / 256), 256>>>(tab);

    // input rmsnorm -> fp16
    rmsnorm_kernel<<<T_, NB>>>(hidden, HID_, ln_in, hh, HID_, HID_);
    // fused [q_a | ckv] = h @ [w_q_a ; w_kv_a]^T (split fp32 outputs)
    gemm_h<<<grid2(T_, NCAT_), GB, SH>>>(hh, HID_, 0, wcat, HID_, 0, qa, 0, 0, ckv,
                                         T_, NCAT_, HID_, 0, 5);
    rmsnorm_kernel<<<T_, NB>>>(qa, QLR_, ln_q_a, qah, QLR_, QLR_);
    gemm_h<<<grid2(T_, H_ * DQK_), GB, SH>>>(qah, QLR_, 0, wqb, QLR_, 0, qh, H_ * DQK_, 0, nullptr,
                                             T_, H_ * DQK_, QLR_, 0, 1);
    rmsnorm_kernel<<<T_, NB>>>(ckv, KVLR_ + DR_, ln_kv_a, ckvnh, KVLR_, KVLR_);
    gemm_h<<<grid2(T_, H_ * (DN_ + DV_)), GB, SH>>>(ckvnh, KVLR_, 0, wkvb, KVLR_, 0,
                                                    kvh, H_ * (DN_ + DV_), 0, nullptr,
                                                    T_, H_ * (DN_ + DV_), KVLR_, 0, 1);
    rope_pack_kernel<<<dim3(T_, H_), DQK_>>>(qh, kvh, ckv, cosb, sinb, qfh, kfh);
    pack_vt_kernel<<<dim3(T_ / 32, DV_ / 32, H_), dim3(32, 8)>>>(kvh, vth);
    // fused flash attention
    flash_kernel<<<dim3(H_, T_ / 128), 256, FA_SMEM>>>(qfh, kfh, vth, ath);
    // res2 = hidden + attn @ w_o^T (fused residual)
    gemm_h<<<grid2(T_, HID_), GB, SH>>>(ath, H_ * DV_, 0, wo, H_ * DV_, 0, res2, HID_, 0, hidden,
                                        T_, HID_, H_ * DV_, 0, 2);
    rmsnorm_kernel<<<T_, NB>>>(res2, HID_, ln_post, h2h, HID_, HID_);
    // act = fp16(silu(h2@wg^T) * (h2@wu^T)) with fp32 weights converted in-loader
    gemm_gu<<<dim3(INTER_ / 64, T_ / 128), GB, GU_SMEM>>>(h2h, w_gate, w_up, acth,
                                                          T_, INTER_, HID_);
    // out = res2 + act @ w_down^T with fp32 weight converted in-loader
    gemm_dn<<<grid2(T_, HID_), GB, SH>>>(acth, w_down, out, res2, T_, HID_, INTER_);
}

// round 17
// speedup vs baseline: 1.2440x; 1.2440x over previous
#include <cuda_runtime.h>
#include <cuda_fp16.h>
#include <math.h>
#include <stdint.h>

// ---------------- problem constants ----------------
#define T_    2048
#define HID_  2048
#define H_    16
#define DN_   128
#define DR_   64
#define DQK_  192
#define DV_   128
#define QLR_  1536
#define KVLR_ 512
#define INTER_ 10944
#define EPS_  1e-6f
#define SCALE_ 0.07216878364870323f   // 192^-0.5
#define NCAT_ (QLR_ + KVLR_ + DR_)    // 2112

// ---------------- fp32 scratch ----------------
__device__ float g_qa[(size_t)T_ * QLR_];
__device__ float g_ckv[(size_t)T_ * (KVLR_ + DR_)];
__device__ float g_res2[(size_t)T_ * HID_];
// ---------------- fp16 scratch ----------------
__device__ __half g_hh[(size_t)T_ * HID_];
__device__ __half g_qah[(size_t)T_ * QLR_];
__device__ __half g_ckvnh[(size_t)T_ * KVLR_];
__device__ __half g_qh[(size_t)T_ * H_ * DQK_];
__device__ __half g_kvh[(size_t)T_ * H_ * (DN_ + DV_)];
__device__ __half g_qfullh[(size_t)H_ * T_ * DQK_];
__device__ __half g_kfullh[(size_t)H_ * T_ * DQK_];
__device__ __half g_vth[(size_t)H_ * DV_ * T_];
__device__ __half g_attnh[(size_t)T_ * H_ * DV_];
__device__ __half g_h2h[(size_t)T_ * HID_];
__device__ __half g_acth[(size_t)T_ * INTER_];
// fp16 weights
__device__ __half g_wcat[(size_t)NCAT_ * HID_];     // [w_q_a ; w_kv_a]
__device__ __half g_wqb[(size_t)H_ * DQK_ * QLR_];
__device__ __half g_wkvb[(size_t)H_ * (DN_ + DV_) * KVLR_];
__device__ __half g_wo[(size_t)HID_ * H_ * DV_];
__device__ __half g_wgate[(size_t)INTER_ * HID_];
__device__ __half g_wup[(size_t)INTER_ * HID_];
__device__ __half g_wdown[(size_t)HID_ * INTER_];

// ---------------- helpers ----------------
__device__ __forceinline__ uint32_t smem_u32(const void* p) {
    uint32_t a;
    asm("{ .reg .u64 t; cvta.to.shared.u64 t, %1; cvt.u32.u64 %0, t; }" : "=r"(a) : "l"(p));
    return a;
}
__device__ __forceinline__ void ldsm4(uint32_t addr, uint32_t& r0, uint32_t& r1,
                                      uint32_t& r2, uint32_t& r3) {
    asm volatile("ldmatrix.sync.aligned.m8n8.x4.shared.b16 {%0,%1,%2,%3}, [%4];"
                 : "=r"(r0), "=r"(r1), "=r"(r2), "=r"(r3) : "r"(addr));
}
__device__ __forceinline__ void mma_f16(float* c, const uint32_t* a, const uint32_t* b) {
    asm volatile(
        "mma.sync.aligned.m16n8k16.row.col.f32.f16.f16.f32 "
        "{%0,%1,%2,%3}, {%4,%5,%6,%7}, {%8,%9}, {%0,%1,%2,%3};"
        : "+f"(c[0]), "+f"(c[1]), "+f"(c[2]), "+f"(c[3])
        : "r"(a[0]), "r"(a[1]), "r"(a[2]), "r"(a[3]), "r"(b[0]), "r"(b[1]));
}
__device__ __forceinline__ void cp16(uint32_t smaddr, const void* gaddr, int vbytes) {
    asm volatile("cp.async.cg.shared.global [%0], [%1], 16, %2;"
                 :: "r"(smaddr), "l"(gaddr), "r"(vbytes) : "memory");
}
#define CP_COMMIT() asm volatile("cp.async.commit_group;" ::: "memory")
#define CP_WAIT1()  asm volatile("cp.async.wait_group 1;" ::: "memory")

// ================= fp16 mma.sync GEMM: C = A * B^T =================
// Block 128x128, 4 warps (2x2), warp tile 64x64, BK=64, 3-stage cp.async.
// mode: 0 dense; 2 causal K-truncate.
// emode: 0 fp32 C; 1 half C; 2 fp32 C = acc + R;
//        5 split fp32: col<QLR_ -> Cv[ld=QLR_], else -> R[ld=KVLR_+DR_].
#define GH_A_BYTES 16384
#define GH_STAGE_BYTES 32768
#define GH_SMEM (3 * GH_STAGE_BYTES)

__global__ __launch_bounds__(128, 2) void gemm_h(
    const __half* __restrict__ A, int lda, size_t sA,
    const __half* __restrict__ B, int ldb, size_t sB,
    void* __restrict__ Cv, int ldc, size_t sC,
    const float* __restrict__ R,
    int M, int N, int K, int mode, int emode)
{
    const int bm = blockIdx.y, bn = blockIdx.x, bz = blockIdx.z;
    int kEnd = K;
    if (mode == 2) { int ke = (bm + 1) * 128; kEnd = ke < K ? ke : K; }

    A += (size_t)bz * sA;
    B += (size_t)bz * sB;

    extern __shared__ char smem[];
    const uint32_t smem_base = smem_u32(smem);
    const int tid = threadIdx.x, wid = tid >> 5, lane = tid & 31;
    const int wm = wid & 1, wn = wid >> 1;
    const int row0 = bm * 128, nrow0 = bn * 128;
    const int nIter = kEnd >> 6;

    const int lr = tid >> 3;
    const int lc = tid & 7;
    const uint32_t lsw = (uint32_t)((lc ^ (lr & 7)) << 4);

    auto load_stage = [&](int it, int s) {
        const int k0 = it << 6;
        const uint32_t sA_ = smem_base + s * GH_STAGE_BYTES;
        const uint32_t sB_ = sA_ + GH_A_BYTES;
#pragma unroll
        for (int j = 0; j < 8; j++) {
            const int r = lr + j * 16;
            cp16(sA_ + (uint32_t)r * 128 + lsw,
                 A + (size_t)(row0 + r) * lda + k0 + lc * 8, 16);
        }
#pragma unroll
        for (int j = 0; j < 8; j++) {
            const int r = lr + j * 16;
            const int gr = nrow0 + r;
            cp16(sB_ + (uint32_t)r * 128 + lsw,
                 B + (size_t)(gr < N ? gr : 0) * ldb + k0 + lc * 8, gr < N ? 16 : 0);
        }
        CP_COMMIT();
    };

    float acc[4][8][4];
#pragma unroll
    for (int i = 0; i < 4; i++)
#pragma unroll
        for (int j = 0; j < 8; j++)
#pragma unroll
            for (int l = 0; l < 4; l++) acc[i][j][l] = 0.f;

    load_stage(0, 0);
    if (1 < nIter) load_stage(1, 1); else CP_COMMIT();

    const int l15 = lane & 15;
    const int achk = lane >> 4;
    const int brow_lo = (lane & 7) + ((lane >> 4) << 3);
    const int bchk = (lane >> 3) & 1;

    for (int it = 0; it < nIter; ++it) {
        CP_WAIT1();
        __syncthreads();
        if (it + 2 < nIter) load_stage(it + 2, (it + 2) % 3); else CP_COMMIT();

        const uint32_t bA = smem_base + (it % 3) * GH_STAGE_BYTES;
        const uint32_t bB = bA + GH_A_BYTES;
#pragma unroll
        for (int ks = 0; ks < 4; ks++) {
            uint32_t a[4][4];
#pragma unroll
            for (int mt = 0; mt < 4; mt++) {
                const int row = wm * 64 + mt * 16 + l15;
                const int chk = ks * 2 + achk;
                const uint32_t addr = bA + (uint32_t)row * 128 +
                                      (uint32_t)((chk ^ (row & 7)) << 4);
                ldsm4(addr, a[mt][0], a[mt][1], a[mt][2], a[mt][3]);
            }
            uint32_t b[8][2];
#pragma unroll
            for (int np = 0; np < 4; np++) {
                const int row = wn * 64 + np * 16 + brow_lo;
                const int chk = ks * 2 + bchk;
                const uint32_t addr = bB + (uint32_t)row * 128 +
                                      (uint32_t)((chk ^ (row & 7)) << 4);
                uint32_t q0, q1, q2, q3;
                ldsm4(addr, q0, q1, q2, q3);
                b[np * 2][0] = q0;     b[np * 2][1] = q1;
                b[np * 2 + 1][0] = q2; b[np * 2 + 1][1] = q3;
            }
#pragma unroll
            for (int mt = 0; mt < 4; mt++)
#pragma unroll
                for (int nt = 0; nt < 8; nt++)
                    mma_f16(acc[mt][nt], a[mt], b[nt]);
        }
    }

    // epilogue
    const int g = lane >> 2, t = lane & 3;
    float* Cf = (float*)Cv + (size_t)bz * sC;
    __half* Ch = (__half*)Cv + (size_t)bz * sC;
#pragma unroll
    for (int mt = 0; mt < 4; mt++) {
#pragma unroll
        for (int nt = 0; nt < 8; nt++) {
            const int r0 = row0 + wm * 64 + mt * 16 + g;
            const int c0 = nrow0 + wn * 64 + nt * 8 + 2 * t;
            if (c0 < N) {
                float v0 = acc[mt][nt][0], v1 = acc[mt][nt][1];
                float v2 = acc[mt][nt][2], v3 = acc[mt][nt][3];
                if (emode == 2) {
                    const float2 u0 = *(const float2*)&R[(size_t)r0 * ldc + c0];
                    const float2 u1 = *(const float2*)&R[(size_t)(r0 + 8) * ldc + c0];
                    v0 += u0.x; v1 += u0.y; v2 += u1.x; v3 += u1.y;
                }
                if (emode == 1) {
                    *(__half2*)&Ch[(size_t)r0 * ldc + c0] = __floats2half2_rn(v0, v1);
                    *(__half2*)&Ch[(size_t)(r0 + 8) * ldc + c0] = __floats2half2_rn(v2, v3);
                } else if (emode == 5) {
                    if (c0 < QLR_) {
                        *(float2*)&Cf[(size_t)r0 * QLR_ + c0] = make_float2(v0, v1);
                        *(float2*)&Cf[(size_t)(r0 + 8) * QLR_ + c0] = make_float2(v2, v3);
                    } else {
                        float* Ck = (float*)R;
                        const int cc = c0 - QLR_;
                        *(float2*)&Ck[(size_t)r0 * (KVLR_ + DR_) + cc] = make_float2(v0, v1);
                        *(float2*)&Ck[(size_t)(r0 + 8) * (KVLR_ + DR_) + cc] = make_float2(v2, v3);
                    }
                } else {
                    *(float2*)&Cf[(size_t)r0 * ldc + c0] = make_float2(v0, v1);
                    *(float2*)&Cf[(size_t)(r0 + 8) * ldc + c0] = make_float2(v2, v3);
                }
            }
        }
    }
}

// ======== fused gate/up GEMM: act = fp16(silu(A@Wg^T) * (A@Wu^T)) ========
#define GU_A_BYTES 16384
#define GU_B_BYTES 8192
#define GU_STAGE_BYTES 32768
#define GU_SMEM (3 * GU_STAGE_BYTES)

__global__ __launch_bounds__(128, 2) void gemm_gu(
    const __half* __restrict__ A,
    const __half* __restrict__ Bg,
    const __half* __restrict__ Bu,
    __half* __restrict__ C,
    int M, int N, int K)
{
    const int bm = blockIdx.y, bn = blockIdx.x;
    extern __shared__ char smem[];
    const uint32_t smem_base = smem_u32(smem);
    const int tid = threadIdx.x, wid = tid >> 5, lane = tid & 31;
    const int wm = wid & 1, wn = wid >> 1;
    const int row0 = bm * 128, ncol0 = bn * 64;
    const int nIter = K >> 6;

    const int lr = tid >> 3;
    const int lc = tid & 7;
    const uint32_t lsw = (uint32_t)((lc ^ (lr & 7)) << 4);

    auto load_stage = [&](int it, int s) {
        const int k0 = it << 6;
        const uint32_t sA_ = smem_base + s * GU_STAGE_BYTES;
        const uint32_t sG_ = sA_ + GU_A_BYTES;
        const uint32_t sU_ = sG_ + GU_B_BYTES;
#pragma unroll
        for (int j = 0; j < 8; j++) {
            const int r = lr + j * 16;
            cp16(sA_ + (uint32_t)r * 128 + lsw,
                 A + (size_t)(row0 + r) * K + k0 + lc * 8, 16);
        }
#pragma unroll
        for (int j = 0; j < 4; j++) {
            const int r = lr + j * 16;
            const int gr = ncol0 + r;
            cp16(sG_ + (uint32_t)r * 128 + lsw,
                 Bg + (size_t)gr * K + k0 + lc * 8, 16);
            cp16(sU_ + (uint32_t)r * 128 + lsw,
                 Bu + (size_t)gr * K + k0 + lc * 8, 16);
        }
        CP_COMMIT();
    };

    float accg[4][4][4], accu[4][4][4];
#pragma unroll
    for (int i = 0; i < 4; i++)
#pragma unroll
        for (int j = 0; j < 4; j++)
#pragma unroll
            for (int l = 0; l < 4; l++) { accg[i][j][l] = 0.f; accu[i][j][l] = 0.f; }

    load_stage(0, 0);
    if (1 < nIter) load_stage(1, 1); else CP_COMMIT();

    const int l15 = lane & 15;
    const int achk = lane >> 4;
    const int brow_lo = (lane & 7) + ((lane >> 4) << 3);
    const int bchk = (lane >> 3) & 1;

    for (int it = 0; it < nIter; ++it) {
        CP_WAIT1();
        __syncthreads();
        if (it + 2 < nIter) load_stage(it + 2, (it + 2) % 3); else CP_COMMIT();

        const uint32_t bA = smem_base + (it % 3) * GU_STAGE_BYTES;
        const uint32_t bG = bA + GU_A_BYTES;
        const uint32_t bU = bG + GU_B_BYTES;
#pragma unroll
        for (int ks = 0; ks < 4; ks++) {
            uint32_t a[4][4];
#pragma unroll
            for (int mt = 0; mt < 4; mt++) {
                const int row = wm * 64 + mt * 16 + l15;
                const int chk = ks * 2 + achk;
                const uint32_t addr = bA + (uint32_t)row * 128 +
                                      (uint32_t)((chk ^ (row & 7)) << 4);
                ldsm4(addr, a[mt][0], a[mt][1], a[mt][2], a[mt][3]);
            }
            uint32_t bg[4][2], bu[4][2];
#pragma unroll
            for (int np = 0; np < 2; np++) {
                const int row = wn * 32 + np * 16 + brow_lo;
                const int chk = ks * 2 + bchk;
                const uint32_t swo = (uint32_t)row * 128 + (uint32_t)((chk ^ (row & 7)) << 4);
                uint32_t q0, q1, q2, q3;
                ldsm4(bG + swo, q0, q1, q2, q3);
                bg[np * 2][0] = q0;     bg[np * 2][1] = q1;
                bg[np * 2 + 1][0] = q2; bg[np * 2 + 1][1] = q3;
                ldsm4(bU + swo, q0, q1, q2, q3);
                bu[np * 2][0] = q0;     bu[np * 2][1] = q1;
                bu[np * 2 + 1][0] = q2; bu[np * 2 + 1][1] = q3;
            }
#pragma unroll
            for (int mt = 0; mt < 4; mt++)
#pragma unroll
                for (int nt = 0; nt < 4; nt++) {
                    mma_f16(accg[mt][nt], a[mt], bg[nt]);
                    mma_f16(accu[mt][nt], a[mt], bu[nt]);
                }
        }
    }

    const int g = lane >> 2, t = lane & 3;
#pragma unroll
    for (int mt = 0; mt < 4; mt++) {
#pragma unroll
        for (int nt = 0; nt < 4; nt++) {
            const int r0 = row0 + wm * 64 + mt * 16 + g;
            const int c0 = ncol0 + wn * 32 + nt * 8 + 2 * t;
            float g0 = accg[mt][nt][0], g1 = accg[mt][nt][1];
            float g2 = accg[mt][nt][2], g3 = accg[mt][nt][3];
            float v0 = g0 / (1.f + expf(-g0)) * accu[mt][nt][0];
            float v1 = g1 / (1.f + expf(-g1)) * accu[mt][nt][1];
            float v2 = g2 / (1.f + expf(-g2)) * accu[mt][nt][2];
            float v3 = g3 / (1.f + expf(-g3)) * accu[mt][nt][3];
            *(__half2*)&C[(size_t)r0 * N + c0] = __floats2half2_rn(v0, v1);
            *(__half2*)&C[(size_t)(r0 + 8) * N + c0] = __floats2half2_rn(v2, v3);
        }
    }
}

// ================= fused flash attention =================
#define FA_QP 0
#define FA_KP 49152
#define FA_VP 147456
#define FA_SMEM 212992

__global__ __launch_bounds__(256, 1) void flash_kernel(
    const __half* __restrict__ Qf, const __half* __restrict__ Kf,
    const __half* __restrict__ Vt, __half* __restrict__ O)
{
    const int qb = (int)gridDim.y - 1 - blockIdx.y;
    const int h = blockIdx.x;
    const int nb = qb + 1;
    const int q0 = qb * 128;
    extern __shared__ char smem[];
    const uint32_t sb = smem_u32(smem);
    const int tid = threadIdx.x, wid = tid >> 5, lane = tid & 31;
    const int lr = tid >> 3, lc = tid & 7;

    const __half* Qb = Qf + (size_t)h * T_ * DQK_;
    const __half* Kb = Kf + (size_t)h * T_ * DQK_;
    const __half* Vb = Vt + (size_t)h * DV_ * T_;

    auto swz = [](int row, int chk) -> uint32_t {
        return (uint32_t)(row * 128 + ((chk ^ (row & 7)) << 4));
    };

#pragma unroll
    for (int p = 0; p < 3; p++)
#pragma unroll
        for (int j = 0; j < 4; j++) {
            const int r = lr + j * 32;
            cp16(sb + FA_QP + p * 16384 + swz(r, lc),
                 Qb + (size_t)(q0 + r) * DQK_ + p * 64 + lc * 8, 16);
        }
    auto loadKV = [&](int kb, int st) {
        const int k0 = kb * 128;
#pragma unroll
        for (int p = 0; p < 3; p++)
#pragma unroll
            for (int j = 0; j < 4; j++) {
                const int r = lr + j * 32;
                cp16(sb + FA_KP + st * 49152 + p * 16384 + swz(r, lc),
                     Kb + (size_t)(k0 + r) * DQK_ + p * 64 + lc * 8, 16);
            }
#pragma unroll
        for (int p = 0; p < 2; p++)
#pragma unroll
            for (int j = 0; j < 4; j++) {
                const int dv = lr + j * 32;
                cp16(sb + FA_VP + st * 32768 + p * 16384 + swz(dv, lc),
                     Vb + (size_t)dv * T_ + k0 + p * 64 + lc * 8, 16);
            }
    };
    loadKV(0, 0);
    CP_COMMIT();

    float m0 = -1e30f, m1 = -1e30f, l0 = 0.f, l1 = 0.f;
    float o[16][4];
#pragma unroll
    for (int i = 0; i < 16; i++)
#pragma unroll
        for (int e = 0; e < 4; e++) o[i][e] = 0.f;

    const int l15 = lane & 15;
    const int achk = lane >> 4;
    const int brow_lo = (lane & 7) + ((lane >> 4) << 3);
    const int bchk = (lane >> 3) & 1;
    const int g = lane >> 2, t4 = lane & 3;
    const int rowA = wid * 16 + l15;
    const int gq0 = q0 + wid * 16 + g;

    for (int kb = 0; kb < nb; kb++) {
        if (kb + 1 < nb) loadKV(kb + 1, (kb + 1) & 1);
        CP_COMMIT();
        CP_WAIT1();
        __syncthreads();

        const uint32_t bK = sb + FA_KP + (kb & 1) * 49152;
        const uint32_t bV = sb + FA_VP + (kb & 1) * 32768;

        float sacc[16][4];
#pragma unroll
        for (int i = 0; i < 16; i++)
#pragma unroll
            for (int e = 0; e < 4; e++) sacc[i][e] = 0.f;

#pragma unroll
        for (int p = 0; p < 3; p++) {
            const uint32_t qp = sb + FA_QP + p * 16384;
            const uint32_t kp = bK + p * 16384;
#pragma unroll
            for (int sl = 0; sl < 4; sl++) {
                uint32_t a[4];
                ldsm4(qp + swz(rowA, sl * 2 + achk), a[0], a[1], a[2], a[3]);
                uint32_t b[16][2];
#pragma unroll
                for (int np = 0; np < 8; np++) {
                    uint32_t r0, r1, r2, r3;
                    ldsm4(kp + swz(np * 16 + brow_lo, sl * 2 + bchk), r0, r1, r2, r3);
                    b[2 * np][0] = r0;     b[2 * np][1] = r1;
                    b[2 * np + 1][0] = r2; b[2 * np + 1][1] = r3;
                }
#pragma unroll
                for (int nt = 0; nt < 16; nt++)
                    mma_f16(sacc[nt], a, b[nt]);
            }
        }

        const int k0 = kb * 128;
#pragma unroll
        for (int nt = 0; nt < 16; nt++) {
            const int c = k0 + nt * 8 + 2 * t4;
            float s0 = sacc[nt][0] * SCALE_, s1 = sacc[nt][1] * SCALE_;
            float s2 = sacc[nt][2] * SCALE_, s3 = sacc[nt][3] * SCALE_;
            if (kb == qb) {
                if (c     > gq0)     s0 = -1e30f;
                if (c + 1 > gq0)     s1 = -1e30f;
                if (c     > gq0 + 8) s2 = -1e30f;
                if (c + 1 > gq0 + 8) s3 = -1e30f;
            }
            sacc[nt][0] = s0; sacc[nt][1] = s1; sacc[nt][2] = s2; sacc[nt][3] = s3;
        }
        float mx0 = -1e30f, mx1 = -1e30f;
#pragma unroll
        for (int nt = 0; nt < 16; nt++) {
            mx0 = fmaxf(mx0, fmaxf(sacc[nt][0], sacc[nt][1]));
            mx1 = fmaxf(mx1, fmaxf(sacc[nt][2], sacc[nt][3]));
        }
        mx0 = fmaxf(mx0, __shfl_xor_sync(0xffffffffu, mx0, 1));
        mx0 = fmaxf(mx0, __shfl_xor_sync(0xffffffffu, mx0, 2));
        mx1 = fmaxf(mx1, __shfl_xor_sync(0xffffffffu, mx1, 1));
        mx1 = fmaxf(mx1, __shfl_xor_sync(0xffffffffu, mx1, 2));
        const float mn0 = fmaxf(m0, mx0), mn1 = fmaxf(m1, mx1);
        const float f0 = __expf(m0 - mn0), f1 = __expf(m1 - mn1);
        m0 = mn0; m1 = mn1;
        float rs0 = 0.f, rs1 = 0.f;
#pragma unroll
        for (int nt = 0; nt < 16; nt++) {
            const float p0 = __expf(sacc[nt][0] - mn0);
            const float p1 = __expf(sacc[nt][1] - mn0);
            const float p2 = __expf(sacc[nt][2] - mn1);
            const float p3 = __expf(sacc[nt][3] - mn1);
            sacc[nt][0] = p0; sacc[nt][1] = p1; sacc[nt][2] = p2; sacc[nt][3] = p3;
            rs0 += p0 + p1; rs1 += p2 + p3;
            o[nt][0] *= f0; o[nt][1] *= f0; o[nt][2] *= f1; o[nt][3] *= f1;
        }
        rs0 += __shfl_xor_sync(0xffffffffu, rs0, 1);
        rs0 += __shfl_xor_sync(0xffffffffu, rs0, 2);
        rs1 += __shfl_xor_sync(0xffffffffu, rs1, 1);
        rs1 += __shfl_xor_sync(0xffffffffu, rs1, 2);
        l0 = l0 * f0 + rs0;
        l1 = l1 * f1 + rs1;

#pragma unroll
        for (int s8 = 0; s8 < 8; s8++) {
            uint32_t pa[4];
            __half2 ph0 = __floats2half2_rn(sacc[2 * s8][0], sacc[2 * s8][1]);
            __half2 ph1 = __floats2half2_rn(sacc[2 * s8][2], sacc[2 * s8][3]);
            __half2 ph2 = __floats2half2_rn(sacc[2 * s8 + 1][0], sacc[2 * s8 + 1][1]);
            __half2 ph3 = __floats2half2_rn(sacc[2 * s8 + 1][2], sacc[2 * s8 + 1][3]);
            pa[0] = *(uint32_t*)&ph0; pa[1] = *(uint32_t*)&ph1;
            pa[2] = *(uint32_t*)&ph2; pa[3] = *(uint32_t*)&ph3;
            const int pp = s8 >> 2, chk = (s8 & 3) * 2;
            uint32_t bv[16][2];
#pragma unroll
            for (int np = 0; np < 8; np++) {
                uint32_t r0, r1, r2, r3;
                ldsm4(bV + pp * 16384 + swz(np * 16 + brow_lo, chk + bchk), r0, r1, r2, r3);
                bv[2 * np][0] = r0;     bv[2 * np][1] = r1;
                bv[2 * np + 1][0] = r2; bv[2 * np + 1][1] = r3;
            }
#pragma unroll
            for (int nt = 0; nt < 16; nt++)
                mma_f16(o[nt], pa, bv[nt]);
        }
        __syncthreads();
    }

    const float i0 = 1.f / l0, i1 = 1.f / l1;
    const int r = q0 + wid * 16 + g;
#pragma unroll
    for (int nt = 0; nt < 16; nt++) {
        const int c = h * DV_ + nt * 8 + 2 * t4;
        *(__half2*)&O[(size_t)r * (H_ * DV_) + c] =
            __floats2half2_rn(o[nt][0] * i0, o[nt][1] * i0);
        *(__half2*)&O[(size_t)(r + 8) * (H_ * DV_) + c] =
            __floats2half2_rn(o[nt][2] * i1, o[nt][3] * i1);
    }
}

// ---------- merged fp32 -> fp16 conversion of all weights, one launch ----------
#define CVT_NREG 8
struct CvtTab {
    const float4* src[CVT_NREG];
    uint4* dst[CVT_NREG];
    unsigned long long end[CVT_NREG];
};

__global__ void cvt_all_kernel(CvtTab tab)
{
    const size_t i = (size_t)blockIdx.x * blockDim.x + threadIdx.x;
    if (i >= tab.end[CVT_NREG - 1]) return;
    int r = 0;
    while (i >= tab.end[r]) r++;
    const size_t local = i - (r ? tab.end[r - 1] : 0ull);
    const float4* p = tab.src[r] + 4 * local;
    float4 a = p[0], b = p[1], c = p[2], d = p[3];
    __half2 h0 = __floats2half2_rn(a.x, a.y), h1 = __floats2half2_rn(a.z, a.w);
    __half2 h2 = __floats2half2_rn(b.x, b.y), h3 = __floats2half2_rn(b.z, b.w);
    __half2 h4 = __floats2half2_rn(c.x, c.y), h5 = __floats2half2_rn(c.z, c.w);
    __half2 h6 = __floats2half2_rn(d.x, d.y), h7 = __floats2half2_rn(d.z, d.w);
    uint4 o0, o1;
    o0.x = *(uint32_t*)&h0; o0.y = *(uint32_t*)&h1;
    o0.z = *(uint32_t*)&h2; o0.w = *(uint32_t*)&h3;
    o1.x = *(uint32_t*)&h4; o1.y = *(uint32_t*)&h5;
    o1.z = *(uint32_t*)&h6; o1.w = *(uint32_t*)&h7;
    tab.dst[r][2 * local] = o0;
    tab.dst[r][2 * local + 1] = o1;
}

// ---------------- rmsnorm (float4-vectorized fp32 in -> fp16 out) -------------
__global__ void rmsnorm_kernel(const float* __restrict__ x, int ldx,
                               const float* __restrict__ w,
                               __half* __restrict__ out, int ldo, int dim)
{
    const int row = blockIdx.x;
    const float4* xr = (const float4*)(x + (size_t)row * ldx);
    const float4* w4 = (const float4*)w;
    const int n4 = dim >> 2;
    float4 v[2];
    float ss = 0.f;
    int cnt = 0;
    for (int i = threadIdx.x; i < n4; i += blockDim.x, cnt++) {
        float4 t = xr[i];
        v[cnt] = t;
        ss += t.x * t.x + t.y * t.y + t.z * t.z + t.w * t.w;
    }
    __shared__ float red[256];
    red[threadIdx.x] = ss;
    __syncthreads();
    for (int s = 128; s > 0; s >>= 1) {
        if (threadIdx.x < s) red[threadIdx.x] += red[threadIdx.x + s];
        __syncthreads();
    }
    const float inv = rsqrtf(red[0] / (float)dim + EPS_);
    __half* o = out + (size_t)row * ldo;
    cnt = 0;
    for (int i = threadIdx.x; i < n4; i += blockDim.x, cnt++) {
        const float4 ww = w4[i];
        const float4 t = v[cnt];
        __half2 a = __floats2half2_rn(t.x * inv * ww.x, t.y * inv * ww.y);
        __half2 b = __floats2half2_rn(t.z * inv * ww.z, t.w * inv * ww.w);
        uint2 u;
        u.x = *(uint32_t*)&a; u.y = *(uint32_t*)&b;
        *(uint2*)&o[i * 4] = u;
    }
}

// ---------------- RoPE + pack ----------------
__global__ void rope_pack_kernel(const __half* __restrict__ q,
                                 const __half* __restrict__ kv,
                                 const float* __restrict__ ckv,
                                 const float* __restrict__ cosb,
                                 const float* __restrict__ sinb,
                                 __half* __restrict__ qfull,
                                 __half* __restrict__ kfull)
{
    const int t = blockIdx.x, h = blockIdx.y, j = threadIdx.x;
    const size_t o = ((size_t)h * T_ + t) * DQK_ + j;
    float qv, kvv;
    if (j < DN_) {
        qv  = __half2float(q[(size_t)t * (H_ * DQK_) + h * DQK_ + j]);
        kvv = __half2float(kv[(size_t)t * (H_ * (DN_ + DV_)) + h * (DN_ + DV_) + j]);
    } else {
        const int jj = j - DN_;
        const int p  = (jj < DR_ / 2) ? jj : jj - DR_ / 2;
        const float c = cosb[(size_t)t * DR_ + jj];
        const float s = sinb[(size_t)t * DR_ + jj];
        const size_t qb = (size_t)t * (H_ * DQK_) + h * DQK_ + DN_;
        const size_t kb = (size_t)t * (KVLR_ + DR_) + KVLR_;
        const float qe = __half2float(q[qb + 2 * p]), qo = __half2float(q[qb + 2 * p + 1]);
        const float ke = ckv[kb + 2 * p], ko = ckv[kb + 2 * p + 1];
        if (jj < DR_ / 2) { qv = qe * c - qo * s;  kvv = ke * c - ko * s; }
        else              { qv = qo * c + qe * s;  kvv = ko * c + ke * s; }
    }
    qfull[o] = __float2half_rn(qv);
    kfull[o] = __float2half_rn(kvv);
}

// ---------------- pack V^T via smem transpose ----------------
__global__ void pack_vt_kernel(const __half* __restrict__ kvh, __half* __restrict__ vt)
{
    __shared__ __half tile[32][33];
    const int t0 = blockIdx.x * 32, d0 = blockIdx.y * 32, h = blockIdx.z;
    const int tx = threadIdx.x, ty = threadIdx.y;
    for (int r = ty; r < 32; r += 8)
        tile[r][tx] = kvh[(size_t)(t0 + r) * (H_ * (DN_ + DV_)) + h * (DN_ + DV_) + DN_ + d0 + tx];
    __syncthreads();
    for (int r = ty; r < 32; r += 8)
        vt[((size_t)h * DV_ + d0 + r) * T_ + t0 + tx] = tile[tx][r];
}

// ---------------- host driver ----------------
static inline void* sym(const void* s)
{
    void* p = nullptr;
    cudaGetSymbolAddress(&p, s);
    return p;
}

extern "C" void kernel_launch(void* const* d_in, const int* in_sizes, int n_in,
                              void* d_out, int out_size)
{
    const float* hidden  = (const float*)d_in[0];
    const float* cosb    = (const float*)d_in[1];
    const float* sinb    = (const float*)d_in[2];
    const float* ln_in   = (const float*)d_in[3];
    const float* w_q_a   = (const float*)d_in[4];
    const float* ln_q_a  = (const float*)d_in[5];
    const float* w_q_b   = (const float*)d_in[6];
    const float* w_kv_a  = (const float*)d_in[7];
    const float* ln_kv_a = (const float*)d_in[8];
    const float* w_kv_b  = (const float*)d_in[9];
    const float* w_o     = (const float*)d_in[10];
    const float* ln_post = (const float*)d_in[11];
    const float* w_gate  = (const float*)d_in[12];
    const float* w_up    = (const float*)d_in[13];
    const float* w_down  = (const float*)d_in[14];
    float* out = (float*)d_out;

    float* qa    = (float*)sym(g_qa);
    float* ckv   = (float*)sym(g_ckv);
    float* res2  = (float*)sym(g_res2);
    __half* hh    = (__half*)sym(g_hh);
    __half* qah   = (__half*)sym(g_qah);
    __half* ckvnh = (__half*)sym(g_ckvnh);
    __half* qh    = (__half*)sym(g_qh);
    __half* kvh   = (__half*)sym(g_kvh);
    __half* qfh   = (__half*)sym(g_qfullh);
    __half* kfh   = (__half*)sym(g_kfullh);
    __half* vth   = (__half*)sym(g_vth);
    __half* ath   = (__half*)sym(g_attnh);
    __half* h2h   = (__half*)sym(g_h2h);
    __half* acth  = (__half*)sym(g_acth);
    __half* wcat  = (__half*)sym(g_wcat);
    __half* wqb   = (__half*)sym(g_wqb);
    __half* wkvb  = (__half*)sym(g_wkvb);
    __half* wo    = (__half*)sym(g_wo);
    __half* wgt   = (__half*)sym(g_wgate);
    __half* wup   = (__half*)sym(g_wup);
    __half* wdn   = (__half*)sym(g_wdown);

    cudaFuncSetAttribute(gemm_h, cudaFuncAttributeMaxDynamicSharedMemorySize, GH_SMEM);
    cudaFuncSetAttribute(gemm_gu, cudaFuncAttributeMaxDynamicSharedMemorySize, GU_SMEM);
    cudaFuncSetAttribute(flash_kernel, cudaFuncAttributeMaxDynamicSharedMemorySize, FA_SMEM);

    const int NB = 256;
    const int GB = 128;
    const int SH = GH_SMEM;
    auto grid2 = [](int M, int N) { return dim3((N + 127) / 128, M / 128, 1); };

    // ---- merged weight conversion (single launch, 8 regions) ----
    CvtTab tab;
    const float* srcs[CVT_NREG] = {
        w_q_a, w_kv_a, w_q_b, w_kv_b, w_o, w_gate, w_up, w_down };
    __half* dsts[CVT_NREG] = {
        wcat, wcat + (size_t)QLR_ * HID_, wqb, wkvb, wo, wgt, wup, wdn };
    const size_t sizes[CVT_NREG] = {
        (size_t)QLR_ * HID_, (size_t)(KVLR_ + DR_) * HID_,
        (size_t)H_ * DQK_ * QLR_, (size_t)H_ * (DN_ + DV_) * KVLR_,
        (size_t)HID_ * H_ * DV_, (size_t)INTER_ * HID_,
        (size_t)INTER_ * HID_, (size_t)HID_ * INTER_ };
    unsigned long long acc16 = 0;
    for (int r = 0; r < CVT_NREG; r++) {
        tab.src[r] = (const float4*)srcs[r];
        tab.dst[r] = (uint4*)dsts[r];
        acc16 += sizes[r] / 16;
        tab.end[r] = acc16;
    }
    cvt_all_kernel<<<(unsigned)((acc16 + 255) / 256), 256>>>(tab);

    // input rmsnorm -> fp16
    rmsnorm_kernel<<<T_, NB>>>(hidden, HID_, ln_in, hh, HID_, HID_);
    // fused [q_a | ckv] = h @ [w_q_a ; w_kv_a]^T (split fp32 outputs)
    gemm_h<<<grid2(T_, NCAT_), GB, SH>>>(hh, HID_, 0, wcat, HID_, 0, qa, 0, 0, ckv,
                                         T_, NCAT_, HID_, 0, 5);
    rmsnorm_kernel<<<T_, NB>>>(qa, QLR_, ln_q_a, qah, QLR_, QLR_);
    gemm_h<<<grid2(T_, H_ * DQK_), GB, SH>>>(qah, QLR_, 0, wqb, QLR_, 0, qh, H_ * DQK_, 0, nullptr,
                                             T_, H_ * DQK_, QLR_, 0, 1);
    rmsnorm_kernel<<<T_, NB>>>(ckv, KVLR_ + DR_, ln_kv_a, ckvnh, KVLR_, KVLR_);
    gemm_h<<<grid2(T_, H_ * (DN_ + DV_)), GB, SH>>>(ckvnh, KVLR_, 0, wkvb, KVLR_, 0,
                                                    kvh, H_ * (DN_ + DV_), 0, nullptr,
                                                    T_, H_ * (DN_ + DV_), KVLR_, 0, 1);
    rope_pack_kernel<<<dim3(T_, H_), DQK_>>>(qh, kvh, ckv, cosb, sinb, qfh, kfh);
    pack_vt_kernel<<<dim3(T_ / 32, DV_ / 32, H_), dim3(32, 8)>>>(kvh, vth);
    // fused flash attention
    flash_kernel<<<dim3(H_, T_ / 128), 256, FA_SMEM>>>(qfh, kfh, vth, ath);
    // res2 = hidden + attn @ w_o^T (fused residual)
    gemm_h<<<grid2(T_, HID_), GB, SH>>>(ath, H_ * DV_, 0, wo, H_ * DV_, 0, res2, HID_, 0, hidden,
                                        T_, HID_, H_ * DV_, 0, 2);
    rmsnorm_kernel<<<T_, NB>>>(res2, HID_, ln_post, h2h, HID_, HID_);
    // act = fp16(silu(h2@wg^T) * (h2@wu^T)) (fully fused gate+up, fp16 weights)
    gemm_gu<<<dim3(INTER_ / 64, T_ / 128), GB, GU_SMEM>>>(h2h, wgt, wup, acth,
                                                          T_, INTER_, HID_);
    // out = res2 + act @ w_down^T (fused residual, direct to output)
    gemm_h<<<grid2(T_, HID_), GB, SH>>>(acth, INTER_, 0, wdn, INTER_, 0, out, HID_, 0, res2,
                                        T_, HID_, INTER_, 0, 2);
}